// round 11
// baseline (speedup 1.0000x reference)
#include <cuda_runtime.h>
#include <math.h>

#define B_    32
#define NCH   1024
#define NPTS  4096
#define SPL   4          // splits per batch
#define SPTS  1024       // points per split
#define NBK   256        // radius buckets
#define CPS   32         // chunks per split
#define NCHK  128        // total chunks per batch

__device__ float4 g_sorted[B_ * NPTS];   // [b][s*1024+pos] (x,y,z, idx_bits)
__device__ float  g_chunkub[B_ * NCHK];  // [b][j*4+s] split-s chunk-j radius UB
__device__ int    g_counts[B_ * NPTS];   // winner histogram (zeroed by prep)

typedef unsigned long long ull;

__device__ __forceinline__ unsigned int ordf(float f) {
    unsigned int u = __float_as_uint(f);
    return (u & 0x80000000u) ? ~u : (u | 0x80000000u);
}

// ---------------------------------------------------------------------------
// Kernel 0: per-split prep. grid = 128 (b = blk>>2, s = blk&3), 1024 threads,
// 1 point/thread. Bucket-sort descending by radius within the split, analytic
// chunk UBs from bucket edges, passthrough + g_counts zeroing folded in.
// ---------------------------------------------------------------------------
__global__ void __launch_bounds__(1024) prep_kernel(
    const float* __restrict__ x, float* __restrict__ out_x)
{
    __shared__ int hist[NBK];
    __shared__ int sbase[NBK];
    __shared__ int cur[NBK];
    __shared__ int ubi[CPS];

    const int b    = blockIdx.x >> 2;
    const int s    = blockIdx.x & 3;
    const int t    = threadIdx.x;
    const int lane = t & 31;
    const int wid  = t >> 5;

    if (t < NBK) { hist[t] = 0; cur[t] = 0; }
    if (t < CPS) ubi[t] = 0;

    g_counts[b * NPTS + s * SPTS + t] = 0;     // zero my quarter of counts[b]

    const float* xb = x     + (size_t)b * 3 * NPTS + s * SPTS;
    float*       ob = out_x + (size_t)b * 3 * NPTS + s * SPTS;

    float a = xb[t], c = xb[NPTS + t], d = xb[2 * NPTS + t];
    ob[t] = a; ob[NPTS + t] = c; ob[2 * NPTS + t] = d;       // passthrough

    float r = __fsqrt_ru(__fmaf_rn(a, a, __fmaf_rn(c, c, d * d)));
    int bb = (int)(r * 40.0f);
    bb = bb > 255 ? 255 : bb;
    __syncthreads();                            // zeroing visible to all
    atomicAdd(&hist[bb], 1);
    __syncthreads();

    // exclusive offsets in DESCENDING bucket order (warp 0)
    if (wid == 0) {
        int carry = 0;
        #pragma unroll
        for (int seg = 0; seg < 8; ++seg) {
            int idx = 255 - (seg * 32 + lane);
            int v = hist[idx];
            int sc = v;
            #pragma unroll
            for (int off = 1; off < 32; off <<= 1) {
                int u = __shfl_up_sync(0xffffffffu, sc, off);
                if (lane >= off) sc += u;
            }
            sbase[idx] = sc - v + carry;
            carry += __shfl_sync(0xffffffffu, sc, 31);
        }
    }
    __syncthreads();

    // scatter (order within bucket arbitrary); original batch-index in .w
    {
        int pos = sbase[bb] + atomicAdd(&cur[bb], 1);
        g_sorted[(size_t)b * NPTS + s * SPTS + pos] =
            make_float4(a, c, d, __uint_as_float((unsigned)(s * SPTS + t)));
    }

    // analytic chunk UBs from bucket edges (descending layout makes them
    // automatically bound all later chunks of this split too)
    if (t < NBK) {
        int st = sbase[t], h = hist[t];
        if (h > 0) {
            float edge = (t == 255) ? 3.0e38f : (float)(t + 1) * 0.025f * 1.001f;
            int c0 = st >> 5, c1 = (st + h - 1) >> 5;
            for (int cc = c0; cc <= c1; ++cc)
                atomicMax(&ubi[cc], __float_as_int(edge));   // nonneg: int max ok
        }
    }
    __syncthreads();
    if (t < CPS) g_chunkub[b * NCHK + t * SPL + s] = __int_as_float(ubi[t]);
}

// ---------------------------------------------------------------------------
// Kernel 1: pruned argmax. WARP = channel, lanes = points. Rounds of 4 chunks
// (one per split, interleaved); remaining-bound = column max of next chunk
// across splits (monotone since each split is descending). Winner histogram
// accumulated directly into g_counts. Exact fp32 first-index argmax.
// grid = 4096 (32 b x 128), 256 threads (8 channels/block).
// ---------------------------------------------------------------------------
__global__ void __launch_bounds__(256) argmax_kernel(const float* __restrict__ W)
{
    __shared__ float scub[NCHK];

    const int b    = blockIdx.x >> 7;
    const int loc  = blockIdx.x & 127;
    const int lane = threadIdx.x & 31;
    const int wid  = threadIdx.x >> 5;
    const int c    = loc * 8 + wid;

    if (threadIdx.x < NCHK) scub[threadIdx.x] = g_chunkub[b * NCHK + threadIdx.x];
    __syncthreads();

    const float w0 = W[c * 3 + 0];
    const float w1 = W[c * 3 + 1];
    const float w2 = W[c * 3 + 2];
    const float wn = __fsqrt_ru(__fmaf_ru(w0, w0,
                      __fmaf_ru(w1, w1, __fmul_ru(w2, w2)))) * 1.00002f;

    // lane j holds colmax[j] = max over splits of chunk-j UB
    const float cm = fmaxf(fmaxf(scub[lane * 4 + 0], scub[lane * 4 + 1]),
                           fmaxf(scub[lane * 4 + 2], scub[lane * 4 + 3]));

    const float4* sp = g_sorted + (size_t)b * NPTS;

    unsigned bestu = 0;          // warp-uniform ordf(best)
    ull      kbest = 0;          // per-lane (ordf(f)<<32)|(4095-idx)

    #pragma unroll 1
    for (int j = 0; j < CPS; ++j) {
        unsigned kmax = 0;
        #pragma unroll
        for (int s = 0; s < SPL; ++s) {
            float4 p = sp[s * SPTS + (j << 5) + lane];       // coalesced 512B
            float f = __fmaf_rn(w2, p.z, __fmaf_rn(w1, p.y, __fmul_rn(w0, p.x)));
            unsigned k32 = ordf(f);
            ull key = ((ull)k32 << 32) | (ull)(4095u - __float_as_uint(p.w));
            kbest = kbest > key ? kbest : key;
            kmax  = kmax  > k32 ? kmax  : k32;
        }
        bestu = max(bestu, __reduce_max_sync(0xffffffffu, kmax));
        if (j + 1 < CPS) {
            float nb = __shfl_sync(0xffffffffu, cm, j + 1);  // next-round bound
            if (ordf(nb * wn) < bestu) break;                // no remaining beat/tie
        }
    }

    #pragma unroll
    for (int o = 16; o; o >>= 1) {
        ull other = __shfl_xor_sync(0xffffffffu, kbest, o);
        kbest = kbest > other ? kbest : other;
    }
    if (lane == 0)
        atomicAdd(&g_counts[b * NPTS + (4095 - (int)(kbest & 0xFFFu))], 1);
}

// ---------------------------------------------------------------------------
// Kernel 2: counts out, entropy, parallel stable counting sort.
// grid = 32, 1024 threads, 63.5KB dynamic smem. Histogram comes prebuilt
// from argmax via g_counts (prefetched as int4).
// ---------------------------------------------------------------------------
__global__ void __launch_bounds__(1024) sort_entropy_kernel(
    float* __restrict__ out_counts,
    float* __restrict__ out_imp2,
    float* __restrict__ out_ent)
{
    extern __shared__ __align__(16) char smem_raw[];
    int*            scnt   = (int*)smem_raw;
    int*            gstart = (int*)(smem_raw + 16384);
    unsigned short* chh    = (unsigned short*)(smem_raw + 20488);  // 1025*17 u16
    unsigned short* lrk    = (unsigned short*)(smem_raw + 55340);  // 4096 u16
    __shared__ float red[32];
    __shared__ int   ired[32];

    const int b    = blockIdx.x;
    const int t    = threadIdx.x;
    const int lane = t & 31;
    const int wid  = t >> 5;

    // prefetch counts (LDG issues before the smem zero loop)
    const int4 cv = ((const int4*)(g_counts + (size_t)b * NPTS))[t];

    for (int i = t; i < 8713; i += 1024) ((unsigned*)chh)[i] = 0;
    ((int4*)scnt)[t] = cv;
    __syncthreads();

    // counts out (float4) + entropy partial (sum analytically = 1024 + 4096e-6)
    const float inv_s = 1.0f / (1024.0f + 4096.0f * 1e-6f);
    float part2;
    {
        float4 cf = make_float4((float)cv.x, (float)cv.y, (float)cv.z, (float)cv.w);
        ((float4*)(out_counts + (size_t)b * NPTS))[t] = cf;
        float p0 = (cf.x + 1e-6f) * inv_s, p1 = (cf.y + 1e-6f) * inv_s;
        float p2 = (cf.z + 1e-6f) * inv_s, p3 = (cf.w + 1e-6f) * inv_s;
        part2 = p0 * __log2f(p0) + p1 * __log2f(p1)
              + p2 * __log2f(p2) + p3 * __log2f(p3);
    }

    // per-chunk stable local ranks (16 warps, chunk = 256 pts, 8 rounds)
    if (wid < 16) {
        #pragma unroll 1
        for (int r = 0; r < 8; ++r) {
            int n = (wid << 8) + (r << 5) + lane;
            int v = scnt[n];
            unsigned peers = __match_any_sync(0xffffffffu, v);
            int lr = __popc(peers & ((1u << lane) - 1u));
            int base = chh[v * 17 + wid];
            lrk[n] = (unsigned short)(base + lr);
            if (lane == (__ffs(peers) - 1))
                chh[v * 17 + wid] = (unsigned short)(base + __popc(peers));
            __syncwarp();
        }
    }
    __syncthreads();

    // entropy reduction
    #pragma unroll
    for (int o = 16; o; o >>= 1) part2 += __shfl_down_sync(0xffffffffu, part2, o);
    if (lane == 0) red[wid] = part2;
    __syncthreads();
    if (wid == 0) {
        float v = red[lane];
        #pragma unroll
        for (int o = 16; o; o >>= 1) v += __shfl_down_sync(0xffffffffu, v, o);
        if (lane == 0) out_ent[b] = -v * (1.0f / 12.0f);   // log2(4096)=12
    }

    // per-value prefix across 16 chunks (thread t <-> value t)
    int tot;
    {
        int run = 0;
        #pragma unroll
        for (int w = 0; w < 16; ++w) {
            int cc = chh[t * 17 + w];
            chh[t * 17 + w] = (unsigned short)run;
            run += cc;
        }
        tot = run;
        if (t == 0) {    // value 1024
            int r2 = 0;
            #pragma unroll
            for (int w = 0; w < 16; ++w) {
                int cc = chh[1024 * 17 + w];
                chh[1024 * 17 + w] = (unsigned short)r2;
                r2 += cc;
            }
            gstart[1024] = 4096 - r2;
        }
    }

    // parallel exclusive scan of value totals (0..1023)
    int incl = tot;
    #pragma unroll
    for (int o = 1; o < 32; o <<= 1) {
        int u = __shfl_up_sync(0xffffffffu, incl, o);
        if (lane >= o) incl += u;
    }
    if (lane == 31) ired[wid] = incl;
    __syncthreads();
    if (wid == 0) {
        int v = ired[lane];
        int sc = v;
        #pragma unroll
        for (int o = 1; o < 32; o <<= 1) {
            int u = __shfl_up_sync(0xffffffffu, sc, o);
            if (lane >= o) sc += u;
        }
        ired[lane] = sc - v;
    }
    __syncthreads();
    gstart[t] = incl - tot + ired[wid];
    __syncthreads();

    // scatter final ranks
    #pragma unroll
    for (int n = t; n < NPTS; n += 1024) {
        int v = scnt[n];
        int rank = gstart[v] + (int)chh[v * 17 + (n >> 8)] + (int)lrk[n];
        out_imp2[(size_t)b * NPTS + rank] = (float)n;
    }
}

// ---------------------------------------------------------------------------
extern "C" void kernel_launch(void* const* d_in, const int* in_sizes, int n_in,
                              void* d_out, int out_size)
{
    const float* x = (const float*)d_in[0];   // [32, 3, 4096]
    const float* W = (const float*)d_in[1];   // [1024, 3]
    float* out = (float*)d_out;

    float* out_x      = out;
    float* out_counts = out + B_ * 3 * NPTS;
    float* out_imp2   = out_counts + B_ * NPTS;
    float* out_ent    = out_imp2 + B_ * NPTS;

    const int SORT_SMEM = 63552;
    cudaFuncSetAttribute(sort_entropy_kernel,
                         cudaFuncAttributeMaxDynamicSharedMemorySize, SORT_SMEM);

    prep_kernel<<<B_ * SPL, 1024>>>(x, out_x);
    argmax_kernel<<<B_ * 128, 256>>>(W);
    sort_entropy_kernel<<<B_, 1024, SORT_SMEM>>>(out_counts, out_imp2, out_ent);
}

// round 12
// speedup vs baseline: 1.0568x; 1.0568x over previous
#include <cuda_runtime.h>
#include <math.h>

#define B_    32
#define NCH   1024
#define NPTS  4096
#define NBK   256        // radius buckets
#define NCHK  128        // 32-pt chunks per batch

__device__ float4 g_sorted[B_ * NPTS];   // (x,y,z, idx_bits) desc-radius order
__device__ float  g_chunkub[B_ * NCHK];  // radius UB per chunk (suffix-valid)
__device__ int    g_counts[B_ * NPTS];   // winner histogram (zeroed by prep)

typedef unsigned long long ull;

__device__ __forceinline__ unsigned int ordf(float f) {
    unsigned int u = __float_as_uint(f);
    return (u & 0x80000000u) ? ~u : (u | 0x80000000u);
}

// ---------------------------------------------------------------------------
// Kernel 0: per-batch prep, ATOMIC-FREE bucket sort (descending radius).
// grid = 32, 1024 threads, 4 points/thread (float4-vectorized).
// Per-warp histograms via match_any; rank = sbase + warp-prefix + lane-rank.
// Chunk UBs written inline at chunk-start positions. Also zeroes g_counts
// and writes the x passthrough.
// ---------------------------------------------------------------------------
__global__ void __launch_bounds__(1024) prep_kernel(
    const float* __restrict__ x, float* __restrict__ out_x)
{
    __shared__ unsigned short hw[NBK * 33];   // per-(bucket, warp) counts/prefix
    __shared__ int tot[NBK];
    __shared__ int sbase[NBK];

    const int b    = blockIdx.x;
    const int t    = threadIdx.x;
    const int lane = t & 31;
    const int wid  = t >> 5;

    // zero warp-hist (8448 u16 = 4224 u32)
    #pragma unroll
    for (int i = t; i < 4224; i += 1024) ((unsigned*)hw)[i] = 0;
    // zero this batch's counts
    ((int4*)(g_counts + (size_t)b * NPTS))[t] = make_int4(0, 0, 0, 0);

    const float4* x0 = (const float4*)(x + (size_t)b * 3 * NPTS);
    const float4* x1 = x0 + NPTS / 4;
    const float4* x2 = x0 + NPTS / 2;
    float4*       o0 = (float4*)(out_x + (size_t)b * 3 * NPTS);

    float4 X = x0[t], Y = x1[t], Z = x2[t];
    o0[t] = X; o0[NPTS / 4 + t] = Y; o0[NPTS / 2 + t] = Z;   // passthrough

    float px[4] = {X.x, X.y, X.z, X.w};
    float py[4] = {Y.x, Y.y, Y.z, Y.w};
    float pz[4] = {Z.x, Z.y, Z.z, Z.w};
    int   bk[4];
    #pragma unroll
    for (int k = 0; k < 4; ++k) {
        float r = __fsqrt_ru(__fmaf_rn(px[k], px[k],
                   __fmaf_rn(py[k], py[k], pz[k] * pz[k])));
        int bb = (int)(r * 40.0f);
        bk[k] = bb > 255 ? 255 : bb;
    }
    __syncthreads();

    // per-warp histogram + in-warp stable ranks, no atomics
    int myrank[4];
    #pragma unroll
    for (int k = 0; k < 4; ++k) {
        unsigned peers = __match_any_sync(0xffffffffu, bk[k]);
        int lr = __popc(peers & ((1u << lane) - 1u));
        int base = hw[bk[k] * 33 + wid];
        __syncwarp();
        if (lane == (__ffs(peers) - 1))
            hw[bk[k] * 33 + wid] = (unsigned short)(base + __popc(peers));
        __syncwarp();
        myrank[k] = base + lr;
    }
    __syncthreads();

    // per-bucket cross-warp exclusive prefix (thread v < 256), totals -> tot
    if (t < NBK) {
        int run = 0;
        #pragma unroll
        for (int w = 0; w < 32; ++w) {
            int c = hw[t * 33 + w];
            hw[t * 33 + w] = (unsigned short)run;
            run += c;
        }
        tot[t] = run;
    }
    __syncthreads();

    // DESCENDING exclusive scan of bucket totals (warp 0)
    if (wid == 0) {
        int carry = 0;
        #pragma unroll
        for (int seg = 0; seg < 8; ++seg) {
            int idx = 255 - (seg * 32 + lane);
            int v = tot[idx];
            int sc = v;
            #pragma unroll
            for (int off = 1; off < 32; off <<= 1) {
                int u = __shfl_up_sync(0xffffffffu, sc, off);
                if (lane >= off) sc += u;
            }
            sbase[idx] = sc - v + carry;
            carry += __shfl_sync(0xffffffffu, sc, 31);
        }
    }
    __syncthreads();

    // scatter; chunk-start positions also emit the chunk UB (bucket edge)
    #pragma unroll
    for (int k = 0; k < 4; ++k) {
        int p   = t * 4 + k;
        int bb  = bk[k];
        int pos = sbase[bb] + (int)hw[bb * 33 + wid] + myrank[k];
        g_sorted[(size_t)b * NPTS + pos] =
            make_float4(px[k], py[k], pz[k], __uint_as_float((unsigned)p));
        if (!(pos & 31)) {
            float edge = (bb >= 255) ? 3.0e38f
                                     : (float)(bb + 1) * 0.025f * 1.001f;
            g_chunkub[b * NCHK + (pos >> 5)] = edge;
        }
    }
}

// ---------------------------------------------------------------------------
// Kernel 1: pruned argmax (R9-proven structure). WARP = channel, lanes = 32
// points/chunk, whole-batch descending order; warp-uniform early exit.
// Winner histogrammed directly into g_counts. Exact fp32 first-index argmax.
// grid = 4096 (32 b x 128), 256 threads (8 channels/block).
// ---------------------------------------------------------------------------
__global__ void __launch_bounds__(256) argmax_kernel(const float* __restrict__ W)
{
    __shared__ float cub[NCHK];

    const int b    = blockIdx.x >> 7;
    const int loc  = blockIdx.x & 127;
    const int lane = threadIdx.x & 31;
    const int wid  = threadIdx.x >> 5;
    const int c    = loc * 8 + wid;

    if (threadIdx.x < NCHK) cub[threadIdx.x] = g_chunkub[b * NCHK + threadIdx.x];
    __syncthreads();

    const float w0 = W[c * 3 + 0];
    const float w1 = W[c * 3 + 1];
    const float w2 = W[c * 3 + 2];
    const float wn = __fsqrt_ru(__fmaf_ru(w0, w0,
                      __fmaf_ru(w1, w1, __fmul_ru(w2, w2)))) * 1.00002f;

    const float4* sp = g_sorted + (size_t)b * NPTS;

    unsigned bestu = 0;          // warp-uniform ordf(best)
    ull      kbest = 0;          // per-lane (ordf(f)<<32)|(4095-idx)

    #pragma unroll 1
    for (int ck = 0; ck < NCHK; ++ck) {
        float4 p = sp[(ck << 5) + lane];            // coalesced 512B
        float f = __fmaf_rn(w2, p.z, __fmaf_rn(w1, p.y, __fmul_rn(w0, p.x)));
        unsigned k32 = ordf(f);
        ull key = ((ull)k32 << 32) | (ull)(4095u - __float_as_uint(p.w));
        kbest = kbest > key ? kbest : key;

        unsigned m = __reduce_max_sync(0xffffffffu, k32);
        bestu = bestu > m ? bestu : m;

        if (ck + 1 < NCHK) {
            if (ordf(cub[ck + 1] * wn) < bestu) break;   // no remaining beat/tie
        }
    }

    #pragma unroll
    for (int o = 16; o; o >>= 1) {
        ull other = __shfl_xor_sync(0xffffffffu, kbest, o);
        kbest = kbest > other ? kbest : other;
    }
    if (lane == 0)
        atomicAdd(&g_counts[b * NPTS + (4095 - (int)(kbest & 0xFFFu))], 1);
}

// ---------------------------------------------------------------------------
// Kernel 2: counts out, entropy, parallel stable counting sort (R11-proven).
// grid = 32, 1024 threads, 63.5KB dynamic smem.
// ---------------------------------------------------------------------------
__global__ void __launch_bounds__(1024) sort_entropy_kernel(
    float* __restrict__ out_counts,
    float* __restrict__ out_imp2,
    float* __restrict__ out_ent)
{
    extern __shared__ __align__(16) char smem_raw[];
    int*            scnt   = (int*)smem_raw;
    int*            gstart = (int*)(smem_raw + 16384);
    unsigned short* chh    = (unsigned short*)(smem_raw + 20488);  // 1025*17 u16
    unsigned short* lrk    = (unsigned short*)(smem_raw + 55340);  // 4096 u16
    __shared__ float red[32];
    __shared__ int   ired[32];

    const int b    = blockIdx.x;
    const int t    = threadIdx.x;
    const int lane = t & 31;
    const int wid  = t >> 5;

    // prefetch counts (LDG issues before the smem zero loop)
    const int4 cv = ((const int4*)(g_counts + (size_t)b * NPTS))[t];

    for (int i = t; i < 8713; i += 1024) ((unsigned*)chh)[i] = 0;
    ((int4*)scnt)[t] = cv;
    __syncthreads();

    // counts out (float4) + entropy partial (sum analytically = 1024 + 4096e-6)
    const float inv_s = 1.0f / (1024.0f + 4096.0f * 1e-6f);
    float part2;
    {
        float4 cf = make_float4((float)cv.x, (float)cv.y, (float)cv.z, (float)cv.w);
        ((float4*)(out_counts + (size_t)b * NPTS))[t] = cf;
        float p0 = (cf.x + 1e-6f) * inv_s, p1 = (cf.y + 1e-6f) * inv_s;
        float p2 = (cf.z + 1e-6f) * inv_s, p3 = (cf.w + 1e-6f) * inv_s;
        part2 = p0 * __log2f(p0) + p1 * __log2f(p1)
              + p2 * __log2f(p2) + p3 * __log2f(p3);
    }

    // per-chunk stable local ranks (16 warps, chunk = 256 pts, 8 rounds)
    if (wid < 16) {
        #pragma unroll 1
        for (int r = 0; r < 8; ++r) {
            int n = (wid << 8) + (r << 5) + lane;
            int v = scnt[n];
            unsigned peers = __match_any_sync(0xffffffffu, v);
            int lr = __popc(peers & ((1u << lane) - 1u));
            int base = chh[v * 17 + wid];
            lrk[n] = (unsigned short)(base + lr);
            if (lane == (__ffs(peers) - 1))
                chh[v * 17 + wid] = (unsigned short)(base + __popc(peers));
            __syncwarp();
        }
    }
    __syncthreads();

    // entropy reduction
    #pragma unroll
    for (int o = 16; o; o >>= 1) part2 += __shfl_down_sync(0xffffffffu, part2, o);
    if (lane == 0) red[wid] = part2;
    __syncthreads();
    if (wid == 0) {
        float v = red[lane];
        #pragma unroll
        for (int o = 16; o; o >>= 1) v += __shfl_down_sync(0xffffffffu, v, o);
        if (lane == 0) out_ent[b] = -v * (1.0f / 12.0f);   // log2(4096)=12
    }

    // per-value prefix across 16 chunks (thread t <-> value t)
    int tot;
    {
        int run = 0;
        #pragma unroll
        for (int w = 0; w < 16; ++w) {
            int cc = chh[t * 17 + w];
            chh[t * 17 + w] = (unsigned short)run;
            run += cc;
        }
        tot = run;
        if (t == 0) {    // value 1024
            int r2 = 0;
            #pragma unroll
            for (int w = 0; w < 16; ++w) {
                int cc = chh[1024 * 17 + w];
                chh[1024 * 17 + w] = (unsigned short)r2;
                r2 += cc;
            }
            gstart[1024] = 4096 - r2;
        }
    }

    // parallel exclusive scan of value totals (0..1023)
    int incl = tot;
    #pragma unroll
    for (int o = 1; o < 32; o <<= 1) {
        int u = __shfl_up_sync(0xffffffffu, incl, o);
        if (lane >= o) incl += u;
    }
    if (lane == 31) ired[wid] = incl;
    __syncthreads();
    if (wid == 0) {
        int v = ired[lane];
        int sc = v;
        #pragma unroll
        for (int o = 1; o < 32; o <<= 1) {
            int u = __shfl_up_sync(0xffffffffu, sc, o);
            if (lane >= o) sc += u;
        }
        ired[lane] = sc - v;
    }
    __syncthreads();
    gstart[t] = incl - tot + ired[wid];
    __syncthreads();

    // scatter final ranks
    #pragma unroll
    for (int n = t; n < NPTS; n += 1024) {
        int v = scnt[n];
        int rank = gstart[v] + (int)chh[v * 17 + (n >> 8)] + (int)lrk[n];
        out_imp2[(size_t)b * NPTS + rank] = (float)n;
    }
}

// ---------------------------------------------------------------------------
extern "C" void kernel_launch(void* const* d_in, const int* in_sizes, int n_in,
                              void* d_out, int out_size)
{
    const float* x = (const float*)d_in[0];   // [32, 3, 4096]
    const float* W = (const float*)d_in[1];   // [1024, 3]
    float* out = (float*)d_out;

    float* out_x      = out;
    float* out_counts = out + B_ * 3 * NPTS;
    float* out_imp2   = out_counts + B_ * NPTS;
    float* out_ent    = out_imp2 + B_ * NPTS;

    const int SORT_SMEM = 63552;
    cudaFuncSetAttribute(sort_entropy_kernel,
                         cudaFuncAttributeMaxDynamicSharedMemorySize, SORT_SMEM);

    prep_kernel<<<B_, 1024>>>(x, out_x);
    argmax_kernel<<<B_ * 128, 256>>>(W);
    sort_entropy_kernel<<<B_, 1024, SORT_SMEM>>>(out_counts, out_imp2, out_ent);
}

// round 13
// speedup vs baseline: 1.0654x; 1.0082x over previous
#include <cuda_runtime.h>
#include <math.h>

#define B_    32
#define NCH   1024
#define NPTS  4096
#define NBK   256        // radius buckets
#define NCHK  128        // 32-pt chunks per batch

__device__ float4 g_sorted[B_ * NPTS];   // (x,y,z, idx_bits) desc-radius order
__device__ float  g_chunkub[B_ * NCHK];  // radius UB per chunk (suffix-valid)
__device__ int    g_counts[B_ * NPTS];   // winner histogram (zeroed by prep)
__device__ int    g_ticket[B_];          // blocks-done counter per batch

typedef unsigned long long ull;

__device__ __forceinline__ unsigned int ordf(float f) {
    unsigned int u = __float_as_uint(f);
    return (u & 0x80000000u) ? ~u : (u | 0x80000000u);
}

// ---------------------------------------------------------------------------
// Kernel 0: per-batch prep (R9-proven). Bucket-sort descending by radius,
// analytic chunk UBs, zero g_counts + g_ticket. grid = 32, 1024 threads.
// ---------------------------------------------------------------------------
__global__ void __launch_bounds__(1024) prep_kernel(const float* __restrict__ x)
{
    __shared__ int hist[NBK];
    __shared__ int sbase[NBK];
    __shared__ int cur[NBK];
    __shared__ int ubi[NCHK];

    const int b    = blockIdx.x;
    const int t    = threadIdx.x;
    const int lane = t & 31;
    const int wid  = t >> 5;

    if (t < NBK) { hist[t] = 0; cur[t] = 0; }
    if (t < NCHK) ubi[t] = 0;
    if (t == 0) g_ticket[b] = 0;
    ((int4*)(g_counts + (size_t)b * NPTS))[t] = make_int4(0, 0, 0, 0);
    __syncthreads();

    const float4* x0 = (const float4*)(x + (size_t)b * 3 * NPTS);
    const float4* x1 = x0 + NPTS / 4;
    const float4* x2 = x0 + NPTS / 2;

    float4 X = x0[t], Y = x1[t], Z = x2[t];

    float px[4] = {X.x, X.y, X.z, X.w};
    float py[4] = {Y.x, Y.y, Y.z, Y.w};
    float pz[4] = {Z.x, Z.y, Z.z, Z.w};
    int   bk[4];
    #pragma unroll
    for (int k = 0; k < 4; ++k) {
        float r = __fsqrt_ru(__fmaf_rn(px[k], px[k],
                   __fmaf_rn(py[k], py[k], pz[k] * pz[k])));
        int bb = (int)(r * 40.0f);
        bk[k] = bb > 255 ? 255 : bb;
        atomicAdd(&hist[bk[k]], 1);
    }
    __syncthreads();

    // exclusive offsets in DESCENDING bucket order (warp 0)
    if (wid == 0) {
        int carry = 0;
        #pragma unroll
        for (int seg = 0; seg < 8; ++seg) {
            int idx = 255 - (seg * 32 + lane);
            int v = hist[idx];
            int sc = v;
            #pragma unroll
            for (int off = 1; off < 32; off <<= 1) {
                int u = __shfl_up_sync(0xffffffffu, sc, off);
                if (lane >= off) sc += u;
            }
            sbase[idx] = sc - v + carry;
            carry += __shfl_sync(0xffffffffu, sc, 31);
        }
    }
    __syncthreads();

    // scatter (order within bucket arbitrary); original index in .w
    #pragma unroll
    for (int k = 0; k < 4; ++k) {
        int p = t * 4 + k;
        int pos = sbase[bk[k]] + atomicAdd(&cur[bk[k]], 1);
        g_sorted[(size_t)b * NPTS + pos] =
            make_float4(px[k], py[k], pz[k], __uint_as_float((unsigned)p));
    }

    // analytic chunk UBs from bucket edges (descending layout -> suffix-valid)
    if (t < NBK) {
        int st = sbase[t], h = hist[t];
        if (h > 0) {
            float edge = (t == 255) ? 3.0e38f : (float)(t + 1) * 0.025f * 1.001f;
            int c0 = st >> 5, c1 = (st + h - 1) >> 5;
            for (int cc = c0; cc <= c1; ++cc)
                atomicMax(&ubi[cc], __float_as_int(edge));   // nonneg: int max ok
        }
    }
    __syncthreads();
    if (t < NCHK) g_chunkub[b * NCHK + t] = __int_as_float(ubi[t]);
}

// ---------------------------------------------------------------------------
// Kernel 1 (FUSED): pruned argmax + last-block sort/entropy.
// grid = 1024 (32 b x 32 blocks), 1024 threads (32 warps = 32 channels).
// Each block also copies 1/32 of the x passthrough. Last block per batch
// (ticket) runs the counting sort for that batch.
// ---------------------------------------------------------------------------
__global__ void __launch_bounds__(1024) fused_kernel(
    const float* __restrict__ x, const float* __restrict__ W,
    float* __restrict__ out_x,
    float* __restrict__ out_counts,
    float* __restrict__ out_imp2,
    float* __restrict__ out_ent)
{
    extern __shared__ __align__(16) char smem_raw[];
    int*            scnt   = (int*)smem_raw;
    int*            gstart = (int*)(smem_raw + 16384);
    unsigned short* chh    = (unsigned short*)(smem_raw + 20488);  // 1025*17 u16
    unsigned short* lrk    = (unsigned short*)(smem_raw + 55340);  // 4096 u16
    __shared__ float cub[NCHK];
    __shared__ float red[32];
    __shared__ int   ired[32];
    __shared__ int   s_ret;

    const int b    = blockIdx.x >> 5;
    const int loc  = blockIdx.x & 31;
    const int t    = threadIdx.x;
    const int lane = t & 31;
    const int wid  = t >> 5;
    const int c    = loc * 32 + wid;

    // x passthrough: this block copies 96 float4s of batch b
    if (t < 96) {
        const float4* src = (const float4*)x;
        ((float4*)out_x)[(size_t)b * 3072 + loc * 96 + t] =
            src[(size_t)b * 3072 + loc * 96 + t];
    }
    if (t < NCHK) cub[t] = g_chunkub[b * NCHK + t];
    __syncthreads();

    // ---- pruned argmax (R9/R12-proven), warp = channel ----
    {
        const float w0 = W[c * 3 + 0];
        const float w1 = W[c * 3 + 1];
        const float w2 = W[c * 3 + 2];
        const float wn = __fsqrt_ru(__fmaf_ru(w0, w0,
                          __fmaf_ru(w1, w1, __fmul_ru(w2, w2)))) * 1.00002f;

        const float4* sp = g_sorted + (size_t)b * NPTS;

        unsigned bestu = 0;          // warp-uniform ordf(best)
        ull      kbest = 0;          // per-lane (ordf(f)<<32)|(4095-idx)

        #pragma unroll 1
        for (int ck = 0; ck < NCHK; ++ck) {
            float4 p = sp[(ck << 5) + lane];            // coalesced 512B
            float f = __fmaf_rn(w2, p.z, __fmaf_rn(w1, p.y, __fmul_rn(w0, p.x)));
            unsigned k32 = ordf(f);
            ull key = ((ull)k32 << 32) | (ull)(4095u - __float_as_uint(p.w));
            kbest = kbest > key ? kbest : key;

            unsigned m = __reduce_max_sync(0xffffffffu, k32);
            bestu = bestu > m ? bestu : m;

            if (ck + 1 < NCHK) {
                if (ordf(cub[ck + 1] * wn) < bestu) break;   // no remaining beat/tie
            }
        }

        #pragma unroll
        for (int o = 16; o; o >>= 1) {
            ull other = __shfl_xor_sync(0xffffffffu, kbest, o);
            kbest = kbest > other ? kbest : other;
        }
        if (lane == 0) {
            atomicAdd(&g_counts[b * NPTS + (4095 - (int)(kbest & 0xFFFu))], 1);
            __threadfence();     // release my histogram update (gpu scope)
        }
    }
    __syncthreads();
    if (t == 0) s_ret = atomicAdd(&g_ticket[b], 1);
    __syncthreads();
    if (s_ret != 31) return;

    // =================== last block of batch b: sort phase ===================
    // all 32 blocks' counts atomicAdds happen-before the 31st ticket increment
    // (threadFenceReduction pattern); read through L2 with __ldcg.
    const int4 cv = __ldcg((const int4*)(g_counts + (size_t)b * NPTS) + t);

    for (int i = t; i < 8713; i += 1024) ((unsigned*)chh)[i] = 0;
    ((int4*)scnt)[t] = cv;
    __syncthreads();

    // counts out (float4) + entropy partial (sum analytically = 1024 + 4096e-6)
    const float inv_s = 1.0f / (1024.0f + 4096.0f * 1e-6f);
    float part2;
    {
        float4 cf = make_float4((float)cv.x, (float)cv.y, (float)cv.z, (float)cv.w);
        ((float4*)(out_counts + (size_t)b * NPTS))[t] = cf;
        float p0 = (cf.x + 1e-6f) * inv_s, p1 = (cf.y + 1e-6f) * inv_s;
        float p2 = (cf.z + 1e-6f) * inv_s, p3 = (cf.w + 1e-6f) * inv_s;
        part2 = p0 * __log2f(p0) + p1 * __log2f(p1)
              + p2 * __log2f(p2) + p3 * __log2f(p3);
    }

    // per-chunk stable local ranks (16 warps, chunk = 256 pts, 8 rounds)
    if (wid < 16) {
        #pragma unroll 1
        for (int r = 0; r < 8; ++r) {
            int n = (wid << 8) + (r << 5) + lane;
            int v = scnt[n];
            unsigned peers = __match_any_sync(0xffffffffu, v);
            int lr = __popc(peers & ((1u << lane) - 1u));
            int base = chh[v * 17 + wid];
            lrk[n] = (unsigned short)(base + lr);
            if (lane == (__ffs(peers) - 1))
                chh[v * 17 + wid] = (unsigned short)(base + __popc(peers));
            __syncwarp();
        }
    }
    __syncthreads();

    // entropy reduction
    #pragma unroll
    for (int o = 16; o; o >>= 1) part2 += __shfl_down_sync(0xffffffffu, part2, o);
    if (lane == 0) red[wid] = part2;
    __syncthreads();
    if (wid == 0) {
        float v = red[lane];
        #pragma unroll
        for (int o = 16; o; o >>= 1) v += __shfl_down_sync(0xffffffffu, v, o);
        if (lane == 0) out_ent[b] = -v * (1.0f / 12.0f);   // log2(4096)=12
    }

    // per-value prefix across 16 chunks (thread t <-> value t)
    int tot;
    {
        int run = 0;
        #pragma unroll
        for (int w = 0; w < 16; ++w) {
            int cc = chh[t * 17 + w];
            chh[t * 17 + w] = (unsigned short)run;
            run += cc;
        }
        tot = run;
        if (t == 0) {    // value 1024
            int r2 = 0;
            #pragma unroll
            for (int w = 0; w < 16; ++w) {
                int cc = chh[1024 * 17 + w];
                chh[1024 * 17 + w] = (unsigned short)r2;
                r2 += cc;
            }
            gstart[1024] = 4096 - r2;
        }
    }

    // parallel exclusive scan of value totals (0..1023)
    int incl = tot;
    #pragma unroll
    for (int o = 1; o < 32; o <<= 1) {
        int u = __shfl_up_sync(0xffffffffu, incl, o);
        if (lane >= o) incl += u;
    }
    if (lane == 31) ired[wid] = incl;
    __syncthreads();
    if (wid == 0) {
        int v = ired[lane];
        int sc = v;
        #pragma unroll
        for (int o = 1; o < 32; o <<= 1) {
            int u = __shfl_up_sync(0xffffffffu, sc, o);
            if (lane >= o) sc += u;
        }
        ired[lane] = sc - v;
    }
    __syncthreads();
    gstart[t] = incl - tot + ired[wid];
    __syncthreads();

    // scatter final ranks
    #pragma unroll
    for (int n = t; n < NPTS; n += 1024) {
        int v = scnt[n];
        int rank = gstart[v] + (int)chh[v * 17 + (n >> 8)] + (int)lrk[n];
        out_imp2[(size_t)b * NPTS + rank] = (float)n;
    }
}

// ---------------------------------------------------------------------------
extern "C" void kernel_launch(void* const* d_in, const int* in_sizes, int n_in,
                              void* d_out, int out_size)
{
    const float* x = (const float*)d_in[0];   // [32, 3, 4096]
    const float* W = (const float*)d_in[1];   // [1024, 3]
    float* out = (float*)d_out;

    float* out_x      = out;
    float* out_counts = out + B_ * 3 * NPTS;
    float* out_imp2   = out_counts + B_ * NPTS;
    float* out_ent    = out_imp2 + B_ * NPTS;

    const int FUSED_SMEM = 63552;
    cudaFuncSetAttribute(fused_kernel,
                         cudaFuncAttributeMaxDynamicSharedMemorySize, FUSED_SMEM);

    prep_kernel<<<B_, 1024>>>(x);
    fused_kernel<<<B_ * 32, 1024, FUSED_SMEM>>>(x, W, out_x,
                                                out_counts, out_imp2, out_ent);
}

// round 14
// speedup vs baseline: 1.2527x; 1.1758x over previous
#include <cuda_runtime.h>
#include <math.h>

#define B_    32
#define NCH   1024
#define NPTS  4096
#define NBK   256        // radius buckets
#define NCHK  128        // 32-pt chunks per batch

__device__ int    g_imp[B_ * NCH];       // winner per (b, c)
__device__ float4 g_sorted[B_ * NPTS];   // (x,y,z, idx_bits) desc-radius order
__device__ float  g_chunkub[B_ * NCHK];  // radius UB per chunk (suffix-valid)

typedef unsigned long long ull;

__device__ __forceinline__ unsigned int ordf(float f) {
    unsigned int u = __float_as_uint(f);
    return (u & 0x80000000u) ? ~u : (u | 0x80000000u);
}

// ---------------------------------------------------------------------------
// Kernel 0: per-batch prep (R9-proven, passthrough removed). Bucket-sort
// descending by radius, analytic chunk UBs. grid = 32, 1024 threads.
// ---------------------------------------------------------------------------
__global__ void __launch_bounds__(1024) prep_kernel(const float* __restrict__ x)
{
    __shared__ int hist[NBK];
    __shared__ int sbase[NBK];
    __shared__ int cur[NBK];
    __shared__ int ubi[NCHK];

    const int b    = blockIdx.x;
    const int t    = threadIdx.x;
    const int lane = t & 31;
    const int wid  = t >> 5;

    if (t < NBK) { hist[t] = 0; cur[t] = 0; }
    if (t < NCHK) ubi[t] = 0;
    __syncthreads();

    const float4* x0 = (const float4*)(x + (size_t)b * 3 * NPTS);
    const float4* x1 = x0 + NPTS / 4;
    const float4* x2 = x0 + NPTS / 2;

    float4 X = x0[t], Y = x1[t], Z = x2[t];

    float px[4] = {X.x, X.y, X.z, X.w};
    float py[4] = {Y.x, Y.y, Y.z, Y.w};
    float pz[4] = {Z.x, Z.y, Z.z, Z.w};
    int   bk[4];
    #pragma unroll
    for (int k = 0; k < 4; ++k) {
        float r = __fsqrt_ru(__fmaf_rn(px[k], px[k],
                   __fmaf_rn(py[k], py[k], pz[k] * pz[k])));
        int bb = (int)(r * 40.0f);
        bk[k] = bb > 255 ? 255 : bb;
        atomicAdd(&hist[bk[k]], 1);
    }
    __syncthreads();

    // exclusive offsets in DESCENDING bucket order (warp 0)
    if (wid == 0) {
        int carry = 0;
        #pragma unroll
        for (int seg = 0; seg < 8; ++seg) {
            int idx = 255 - (seg * 32 + lane);
            int v = hist[idx];
            int sc = v;
            #pragma unroll
            for (int off = 1; off < 32; off <<= 1) {
                int u = __shfl_up_sync(0xffffffffu, sc, off);
                if (lane >= off) sc += u;
            }
            sbase[idx] = sc - v + carry;
            carry += __shfl_sync(0xffffffffu, sc, 31);
        }
    }
    __syncthreads();

    // scatter (order within bucket arbitrary); original index in .w
    #pragma unroll
    for (int k = 0; k < 4; ++k) {
        int p = t * 4 + k;
        int pos = sbase[bk[k]] + atomicAdd(&cur[bk[k]], 1);
        g_sorted[(size_t)b * NPTS + pos] =
            make_float4(px[k], py[k], pz[k], __uint_as_float((unsigned)p));
    }

    // analytic chunk UBs from bucket edges (descending layout -> suffix-valid)
    if (t < NBK) {
        int st = sbase[t], h = hist[t];
        if (h > 0) {
            float edge = (t == 255) ? 3.0e38f : (float)(t + 1) * 0.025f * 1.001f;
            int c0 = st >> 5, c1 = (st + h - 1) >> 5;
            for (int cc = c0; cc <= c1; ++cc)
                atomicMax(&ubi[cc], __float_as_int(edge));   // nonneg: int max ok
        }
    }
    __syncthreads();
    if (t < NCHK) g_chunkub[b * NCHK + t] = __int_as_float(ubi[t]);
}

// ---------------------------------------------------------------------------
// Kernel 1: pruned argmax with depth-2 chunk prefetch + folded passthrough.
// WARP = channel, lanes = 32 points/chunk, whole-batch descending order,
// warp-uniform early exit. Exact fp32 first-index argmax.
// grid = 4096 (32 b x 128), 256 threads (8 channels/block).
// ---------------------------------------------------------------------------
__global__ void __launch_bounds__(256) argmax_kernel(
    const float* __restrict__ x, const float* __restrict__ W,
    float* __restrict__ out_x)
{
    __shared__ float cub[NCHK];

    const int b    = blockIdx.x >> 7;
    const int loc  = blockIdx.x & 127;
    const int lane = threadIdx.x & 31;
    const int wid  = threadIdx.x >> 5;
    const int c    = loc * 8 + wid;

    // x passthrough: this block copies 24 float4s (grid covers all of x)
    {
        int i = (size_t)blockIdx.x * 24 + (threadIdx.x & 255) % 24;
        if ((threadIdx.x >> 5) == (threadIdx.x & 255) / 32) {}  // no-op shape keep
    }
    if (threadIdx.x < 24) {
        size_t i = (size_t)blockIdx.x * 24 + threadIdx.x;
        ((float4*)out_x)[i] = ((const float4*)x)[i];
    }
    if (threadIdx.x < NCHK) cub[threadIdx.x] = g_chunkub[b * NCHK + threadIdx.x];
    __syncthreads();

    const float w0 = W[c * 3 + 0];
    const float w1 = W[c * 3 + 1];
    const float w2 = W[c * 3 + 2];
    const float wn = __fsqrt_ru(__fmaf_ru(w0, w0,
                      __fmaf_ru(w1, w1, __fmul_ru(w2, w2)))) * 1.00002f;

    const float4* sp = g_sorted + (size_t)b * NPTS;

    unsigned bestu = 0;          // warp-uniform ordf(best)
    ull      kbest = 0;          // per-lane (ordf(f)<<32)|(4095-idx)

    // depth-2 software pipeline: loads are speculative & always in-bounds
    float4 pA = sp[lane];
    float4 pB = sp[32 + lane];

    #pragma unroll 1
    for (int ck = 0; ck < NCHK; ++ck) {
        float4 p = pA;
        pA = pB;
        {
            int nx = ck + 2 < NCHK ? ck + 2 : NCHK - 1;
            pB = sp[(nx << 5) + lane];
        }

        float f = __fmaf_rn(w2, p.z, __fmaf_rn(w1, p.y, __fmul_rn(w0, p.x)));
        unsigned k32 = ordf(f);
        ull key = ((ull)k32 << 32) | (ull)(4095u - __float_as_uint(p.w));
        kbest = kbest > key ? kbest : key;

        unsigned m = __reduce_max_sync(0xffffffffu, k32);
        bestu = bestu > m ? bestu : m;

        if (ck + 1 < NCHK) {
            if (ordf(cub[ck + 1] * wn) < bestu) break;   // no remaining beat/tie
        }
    }

    #pragma unroll
    for (int o = 16; o; o >>= 1) {
        ull other = __shfl_xor_sync(0xffffffffu, kbest, o);
        kbest = kbest > other ? kbest : other;
    }
    if (lane == 0)
        g_imp[b * NCH + c] = 4095 - (int)(kbest & 0xFFFu);
}

// ---------------------------------------------------------------------------
// Kernel 2: counts, entropy, parallel stable counting sort (R9-proven).
// grid = 32, 1024 threads, 63.5KB dynamic smem.
// ---------------------------------------------------------------------------
__global__ void __launch_bounds__(1024) sort_entropy_kernel(
    float* __restrict__ out_counts,
    float* __restrict__ out_imp2,
    float* __restrict__ out_ent)
{
    extern __shared__ __align__(16) char smem_raw[];
    int*            scnt   = (int*)smem_raw;
    int*            gstart = (int*)(smem_raw + 16384);
    unsigned short* chh    = (unsigned short*)(smem_raw + 20488);  // 1025*17 u16
    unsigned short* lrk    = (unsigned short*)(smem_raw + 55340);  // 4096 u16
    __shared__ float red[32];
    __shared__ int   ired[32];

    const int b    = blockIdx.x;
    const int t    = threadIdx.x;
    const int lane = t & 31;
    const int wid  = t >> 5;

    const int myimp = g_imp[b * NCH + t];   // prefetch before zeroing

    #pragma unroll
    for (int i = t; i < NPTS; i += 1024) scnt[i] = 0;
    for (int i = t; i < 8713; i += 1024) ((unsigned*)chh)[i] = 0;
    __syncthreads();

    atomicAdd(&scnt[myimp], 1);
    __syncthreads();

    const float inv_s = 1.0f / (1024.0f + 4096.0f * 1e-6f);
    float part2;
    {
        int4 cv = ((const int4*)scnt)[t];
        float4 cf = make_float4((float)cv.x, (float)cv.y, (float)cv.z, (float)cv.w);
        ((float4*)(out_counts + (size_t)b * NPTS))[t] = cf;
        float p0 = (cf.x + 1e-6f) * inv_s, p1 = (cf.y + 1e-6f) * inv_s;
        float p2 = (cf.z + 1e-6f) * inv_s, p3 = (cf.w + 1e-6f) * inv_s;
        part2 = p0 * __log2f(p0) + p1 * __log2f(p1)
              + p2 * __log2f(p2) + p3 * __log2f(p3);
    }

    if (wid < 16) {
        #pragma unroll 1
        for (int r = 0; r < 8; ++r) {
            int n = (wid << 8) + (r << 5) + lane;
            int v = scnt[n];
            unsigned peers = __match_any_sync(0xffffffffu, v);
            int lr = __popc(peers & ((1u << lane) - 1u));
            int base = chh[v * 17 + wid];
            lrk[n] = (unsigned short)(base + lr);
            if (lane == (__ffs(peers) - 1))
                chh[v * 17 + wid] = (unsigned short)(base + __popc(peers));
            __syncwarp();
        }
    }
    __syncthreads();

    #pragma unroll
    for (int o = 16; o; o >>= 1) part2 += __shfl_down_sync(0xffffffffu, part2, o);
    if (lane == 0) red[wid] = part2;
    __syncthreads();
    if (wid == 0) {
        float v = red[lane];
        #pragma unroll
        for (int o = 16; o; o >>= 1) v += __shfl_down_sync(0xffffffffu, v, o);
        if (lane == 0) out_ent[b] = -v * (1.0f / 12.0f);   // log2(4096)=12
    }

    int tot;
    {
        int run = 0;
        #pragma unroll
        for (int w = 0; w < 16; ++w) {
            int cc = chh[t * 17 + w];
            chh[t * 17 + w] = (unsigned short)run;
            run += cc;
        }
        tot = run;
        if (t == 0) {
            int r2 = 0;
            #pragma unroll
            for (int w = 0; w < 16; ++w) {
                int cc = chh[1024 * 17 + w];
                chh[1024 * 17 + w] = (unsigned short)r2;
                r2 += cc;
            }
            gstart[1024] = 4096 - r2;
        }
    }

    int incl = tot;
    #pragma unroll
    for (int o = 1; o < 32; o <<= 1) {
        int u = __shfl_up_sync(0xffffffffu, incl, o);
        if (lane >= o) incl += u;
    }
    if (lane == 31) ired[wid] = incl;
    __syncthreads();
    if (wid == 0) {
        int v = ired[lane];
        int sc = v;
        #pragma unroll
        for (int o = 1; o < 32; o <<= 1) {
            int u = __shfl_up_sync(0xffffffffu, sc, o);
            if (lane >= o) sc += u;
        }
        ired[lane] = sc - v;
    }
    __syncthreads();
    gstart[t] = incl - tot + ired[wid];
    __syncthreads();

    #pragma unroll
    for (int n = t; n < NPTS; n += 1024) {
        int v = scnt[n];
        int rank = gstart[v] + (int)chh[v * 17 + (n >> 8)] + (int)lrk[n];
        out_imp2[(size_t)b * NPTS + rank] = (float)n;
    }
}

// ---------------------------------------------------------------------------
extern "C" void kernel_launch(void* const* d_in, const int* in_sizes, int n_in,
                              void* d_out, int out_size)
{
    const float* x = (const float*)d_in[0];   // [32, 3, 4096]
    const float* W = (const float*)d_in[1];   // [1024, 3]
    float* out = (float*)d_out;

    float* out_x      = out;
    float* out_counts = out + B_ * 3 * NPTS;
    float* out_imp2   = out_counts + B_ * NPTS;
    float* out_ent    = out_imp2 + B_ * NPTS;

    const int SORT_SMEM = 63552;
    cudaFuncSetAttribute(sort_entropy_kernel,
                         cudaFuncAttributeMaxDynamicSharedMemorySize, SORT_SMEM);

    prep_kernel<<<B_, 1024>>>(x);
    argmax_kernel<<<B_ * 128, 256>>>(x, W, out_x);
    sort_entropy_kernel<<<B_, 1024, SORT_SMEM>>>(out_counts, out_imp2, out_ent);
}

// round 15
// speedup vs baseline: 1.2667x; 1.0111x over previous
#include <cuda_runtime.h>
#include <math.h>

#define B_    32
#define NCH   1024
#define NPTS  4096
#define NBK   256        // radius buckets
#define NCHK  128        // 32-pt chunks per batch

__device__ int    g_imp[B_ * NCH];       // winner per (b, c)
__device__ float4 g_sorted[B_ * NPTS];   // (x,y,z, idx_bits) desc-radius order
__device__ float  g_chunkub[B_ * NCHK];  // radius UB per chunk (suffix-valid)

typedef unsigned long long ull;

__device__ __forceinline__ unsigned int ordf(float f) {
    unsigned int u = __float_as_uint(f);
    return (u & 0x80000000u) ? ~u : (u | 0x80000000u);
}

// ---------------------------------------------------------------------------
// Kernel 0: per-batch prep. Bucket-sort descending by radius with SHARED
// STAGING (scatter hits smem banks, global writes fully coalesced).
// grid = 32, 1024 threads, 64KB dynamic smem.
// ---------------------------------------------------------------------------
__global__ void __launch_bounds__(1024) prep_kernel(const float* __restrict__ x)
{
    extern __shared__ __align__(16) float4 stage[];   // 4096 float4 = 64KB
    __shared__ int hist[NBK];
    __shared__ int sbase[NBK];
    __shared__ int cur[NBK];
    __shared__ int ubi[NCHK];

    const int b    = blockIdx.x;
    const int t    = threadIdx.x;
    const int lane = t & 31;
    const int wid  = t >> 5;

    if (t < NBK) { hist[t] = 0; cur[t] = 0; }
    if (t < NCHK) ubi[t] = 0;
    __syncthreads();

    const float4* x0 = (const float4*)(x + (size_t)b * 3 * NPTS);
    const float4* x1 = x0 + NPTS / 4;
    const float4* x2 = x0 + NPTS / 2;

    float4 X = x0[t], Y = x1[t], Z = x2[t];

    float px[4] = {X.x, X.y, X.z, X.w};
    float py[4] = {Y.x, Y.y, Y.z, Y.w};
    float pz[4] = {Z.x, Z.y, Z.z, Z.w};
    int   bk[4];
    #pragma unroll
    for (int k = 0; k < 4; ++k) {
        float r = __fsqrt_ru(__fmaf_rn(px[k], px[k],
                   __fmaf_rn(py[k], py[k], pz[k] * pz[k])));
        int bb = (int)(r * 40.0f);
        bk[k] = bb > 255 ? 255 : bb;
        atomicAdd(&hist[bk[k]], 1);
    }
    __syncthreads();

    // exclusive offsets in DESCENDING bucket order (warp 0)
    if (wid == 0) {
        int carry = 0;
        #pragma unroll
        for (int seg = 0; seg < 8; ++seg) {
            int idx = 255 - (seg * 32 + lane);
            int v = hist[idx];
            int sc = v;
            #pragma unroll
            for (int off = 1; off < 32; off <<= 1) {
                int u = __shfl_up_sync(0xffffffffu, sc, off);
                if (lane >= off) sc += u;
            }
            sbase[idx] = sc - v + carry;
            carry += __shfl_sync(0xffffffffu, sc, 31);
        }
    }
    __syncthreads();

    // scatter into SHARED staging (bank-priced, not wavefront-priced)
    #pragma unroll
    for (int k = 0; k < 4; ++k) {
        int p = t * 4 + k;
        int pos = sbase[bk[k]] + atomicAdd(&cur[bk[k]], 1);
        stage[pos] = make_float4(px[k], py[k], pz[k],
                                 __uint_as_float((unsigned)p));
    }

    // analytic chunk UBs from bucket edges (descending layout -> suffix-valid)
    if (t < NBK) {
        int st = sbase[t], h = hist[t];
        if (h > 0) {
            float edge = (t == 255) ? 3.0e38f : (float)(t + 1) * 0.025f * 1.001f;
            int c0 = st >> 5, c1 = (st + h - 1) >> 5;
            for (int cc = c0; cc <= c1; ++cc)
                atomicMax(&ubi[cc], __float_as_int(edge));   // nonneg: int max ok
        }
    }
    __syncthreads();

    // coalesced write-out of the sorted array
    #pragma unroll
    for (int i = t; i < NPTS; i += 1024)
        g_sorted[(size_t)b * NPTS + i] = stage[i];

    if (t < NCHK) g_chunkub[b * NCHK + t] = __int_as_float(ubi[t]);
}

// ---------------------------------------------------------------------------
// Kernel 1: pruned argmax with depth-2 chunk prefetch + folded passthrough.
// WARP = channel, lanes = 32 points/chunk, whole-batch descending order,
// warp-uniform early exit. Exact fp32 first-index argmax.
// grid = 4096 (32 b x 128), 256 threads (8 channels/block).
// ---------------------------------------------------------------------------
__global__ void __launch_bounds__(256) argmax_kernel(
    const float* __restrict__ x, const float* __restrict__ W,
    float* __restrict__ out_x)
{
    __shared__ float cub[NCHK];

    const int b    = blockIdx.x >> 7;
    const int loc  = blockIdx.x & 127;
    const int lane = threadIdx.x & 31;
    const int wid  = threadIdx.x >> 5;
    const int c    = loc * 8 + wid;

    // x passthrough: this block copies 24 float4s (grid covers all of x)
    if (threadIdx.x < 24) {
        size_t i = (size_t)blockIdx.x * 24 + threadIdx.x;
        ((float4*)out_x)[i] = ((const float4*)x)[i];
    }
    if (threadIdx.x < NCHK) cub[threadIdx.x] = g_chunkub[b * NCHK + threadIdx.x];
    __syncthreads();

    const float w0 = W[c * 3 + 0];
    const float w1 = W[c * 3 + 1];
    const float w2 = W[c * 3 + 2];
    const float wn = __fsqrt_ru(__fmaf_ru(w0, w0,
                      __fmaf_ru(w1, w1, __fmul_ru(w2, w2)))) * 1.00002f;

    const float4* sp = g_sorted + (size_t)b * NPTS;

    unsigned bestu = 0;          // warp-uniform ordf(best)
    ull      kbest = 0;          // per-lane (ordf(f)<<32)|(4095-idx)

    // depth-2 software pipeline: loads are speculative & always in-bounds
    float4 pA = sp[lane];
    float4 pB = sp[32 + lane];

    #pragma unroll 1
    for (int ck = 0; ck < NCHK; ++ck) {
        float4 p = pA;
        pA = pB;
        {
            int nx = ck + 2 < NCHK ? ck + 2 : NCHK - 1;
            pB = sp[(nx << 5) + lane];
        }

        float f = __fmaf_rn(w2, p.z, __fmaf_rn(w1, p.y, __fmul_rn(w0, p.x)));
        unsigned k32 = ordf(f);
        ull key = ((ull)k32 << 32) | (ull)(4095u - __float_as_uint(p.w));
        kbest = kbest > key ? kbest : key;

        unsigned m = __reduce_max_sync(0xffffffffu, k32);
        bestu = bestu > m ? bestu : m;

        if (ck + 1 < NCHK) {
            if (ordf(cub[ck + 1] * wn) < bestu) break;   // no remaining beat/tie
        }
    }

    #pragma unroll
    for (int o = 16; o; o >>= 1) {
        ull other = __shfl_xor_sync(0xffffffffu, kbest, o);
        kbest = kbest > other ? kbest : other;
    }
    if (lane == 0)
        g_imp[b * NCH + c] = 4095 - (int)(kbest & 0xFFFu);
}

// ---------------------------------------------------------------------------
// Kernel 2: counts, entropy, stable counting sort. Final ranks scatter into a
// SHARED u16 permutation, then one coalesced float4 write pass (kills the
// global scatter wavefronts). grid = 32, 1024 threads, ~70KB dynamic smem.
// ---------------------------------------------------------------------------
__global__ void __launch_bounds__(1024) sort_entropy_kernel(
    float* __restrict__ out_counts,
    float* __restrict__ out_imp2,
    float* __restrict__ out_ent)
{
    extern __shared__ __align__(16) char smem_raw[];
    int*            scnt   = (int*)smem_raw;                       // 16384
    int*            gstart = (int*)(smem_raw + 16384);             // 4100
    unsigned short* chh    = (unsigned short*)(smem_raw + 20488);  // 34852
    unsigned short* lrk    = (unsigned short*)(smem_raw + 55340);  // 8192
    unsigned short* sperm  = (unsigned short*)(smem_raw + 63536);  // 8192
    __shared__ float red[32];
    __shared__ int   ired[32];

    const int b    = blockIdx.x;
    const int t    = threadIdx.x;
    const int lane = t & 31;
    const int wid  = t >> 5;

    const int myimp = g_imp[b * NCH + t];   // prefetch before zeroing

    #pragma unroll
    for (int i = t; i < NPTS; i += 1024) scnt[i] = 0;
    for (int i = t; i < 8713; i += 1024) ((unsigned*)chh)[i] = 0;
    __syncthreads();

    atomicAdd(&scnt[myimp], 1);
    __syncthreads();

    const float inv_s = 1.0f / (1024.0f + 4096.0f * 1e-6f);
    float part2;
    {
        int4 cv = ((const int4*)scnt)[t];
        float4 cf = make_float4((float)cv.x, (float)cv.y, (float)cv.z, (float)cv.w);
        ((float4*)(out_counts + (size_t)b * NPTS))[t] = cf;
        float p0 = (cf.x + 1e-6f) * inv_s, p1 = (cf.y + 1e-6f) * inv_s;
        float p2 = (cf.z + 1e-6f) * inv_s, p3 = (cf.w + 1e-6f) * inv_s;
        part2 = p0 * __log2f(p0) + p1 * __log2f(p1)
              + p2 * __log2f(p2) + p3 * __log2f(p3);
    }

    // per-chunk stable local ranks (16 warps, chunk = 256 pts, 8 rounds)
    if (wid < 16) {
        #pragma unroll 1
        for (int r = 0; r < 8; ++r) {
            int n = (wid << 8) + (r << 5) + lane;
            int v = scnt[n];
            unsigned peers = __match_any_sync(0xffffffffu, v);
            int lr = __popc(peers & ((1u << lane) - 1u));
            int base = chh[v * 17 + wid];
            lrk[n] = (unsigned short)(base + lr);
            if (lane == (__ffs(peers) - 1))
                chh[v * 17 + wid] = (unsigned short)(base + __popc(peers));
            __syncwarp();
        }
    }
    __syncthreads();

    // entropy reduction
    #pragma unroll
    for (int o = 16; o; o >>= 1) part2 += __shfl_down_sync(0xffffffffu, part2, o);
    if (lane == 0) red[wid] = part2;
    __syncthreads();
    if (wid == 0) {
        float v = red[lane];
        #pragma unroll
        for (int o = 16; o; o >>= 1) v += __shfl_down_sync(0xffffffffu, v, o);
        if (lane == 0) out_ent[b] = -v * (1.0f / 12.0f);   // log2(4096)=12
    }

    // per-value prefix across 16 chunks (thread t <-> value t)
    int tot;
    {
        int run = 0;
        #pragma unroll
        for (int w = 0; w < 16; ++w) {
            int cc = chh[t * 17 + w];
            chh[t * 17 + w] = (unsigned short)run;
            run += cc;
        }
        tot = run;
        if (t == 0) {
            int r2 = 0;
            #pragma unroll
            for (int w = 0; w < 16; ++w) {
                int cc = chh[1024 * 17 + w];
                chh[1024 * 17 + w] = (unsigned short)r2;
                r2 += cc;
            }
            gstart[1024] = 4096 - r2;
        }
    }

    // parallel exclusive scan of value totals (0..1023)
    int incl = tot;
    #pragma unroll
    for (int o = 1; o < 32; o <<= 1) {
        int u = __shfl_up_sync(0xffffffffu, incl, o);
        if (lane >= o) incl += u;
    }
    if (lane == 31) ired[wid] = incl;
    __syncthreads();
    if (wid == 0) {
        int v = ired[lane];
        int sc = v;
        #pragma unroll
        for (int o = 1; o < 32; o <<= 1) {
            int u = __shfl_up_sync(0xffffffffu, sc, o);
            if (lane >= o) sc += u;
        }
        ired[lane] = sc - v;
    }
    __syncthreads();
    gstart[t] = incl - tot + ired[wid];
    __syncthreads();

    // ranks scatter into SHARED perm (STS.16), then coalesced write-out
    #pragma unroll
    for (int n = t; n < NPTS; n += 1024) {
        int v = scnt[n];
        int rank = gstart[v] + (int)chh[v * 17 + (n >> 8)] + (int)lrk[n];
        sperm[rank] = (unsigned short)n;
    }
    __syncthreads();
    {
        ushort4 s4 = ((const ushort4*)sperm)[t];
        ((float4*)(out_imp2 + (size_t)b * NPTS))[t] =
            make_float4((float)s4.x, (float)s4.y, (float)s4.z, (float)s4.w);
    }
}

// ---------------------------------------------------------------------------
extern "C" void kernel_launch(void* const* d_in, const int* in_sizes, int n_in,
                              void* d_out, int out_size)
{
    const float* x = (const float*)d_in[0];   // [32, 3, 4096]
    const float* W = (const float*)d_in[1];   // [1024, 3]
    float* out = (float*)d_out;

    float* out_x      = out;
    float* out_counts = out + B_ * 3 * NPTS;
    float* out_imp2   = out_counts + B_ * NPTS;
    float* out_ent    = out_imp2 + B_ * NPTS;

    const int PREP_SMEM = 65536;   // float4 stage[4096]
    const int SORT_SMEM = 71744;
    cudaFuncSetAttribute(prep_kernel,
                         cudaFuncAttributeMaxDynamicSharedMemorySize, PREP_SMEM);
    cudaFuncSetAttribute(sort_entropy_kernel,
                         cudaFuncAttributeMaxDynamicSharedMemorySize, SORT_SMEM);

    prep_kernel<<<B_, 1024, PREP_SMEM>>>(x);
    argmax_kernel<<<B_ * 128, 256>>>(x, W, out_x);
    sort_entropy_kernel<<<B_, 1024, SORT_SMEM>>>(out_counts, out_imp2, out_ent);
}